// round 10
// baseline (speedup 1.0000x reference)
#include <cuda_runtime.h>

// KANN_31379031064675 — 2-layer LagrangeKANN.
// Lane owns one sample per 32-group; walks width pairs (w, w+32) over 32 iters.
// BOTH layers use monomial cubic tables (float4 {a0,a1,a2,a3}, 64 KB each,
// idx = e*64 + k, conflict-free LDS.128): eval = 1 load + 3-FMA Horner.
// Element floor via saturate-magic (validated R8):
//   s  = saturate(fma(t, 64/63, -0.5/63))   (FFMA.SAT: clamp(64t-0.5, 0, 63)/63)
//   y  = asm fma(s, 63, 2^23)                (opaque to fast-math)
//   e  = bits(y) & 63                        (in-bounds by construction)
//   xt = fma(t, 128, fma(y, -2, 2^24-1))     (== 128t - 2e - 1, exact)
// 896 threads/block: only ~4096 warp-tasks exist chip-wide, so active warps/SM
// are unchanged vs 1024, but the register ceiling rises 64 -> 73 (more ILP).

__device__ __forceinline__ float magic_fma(float s) {
    float y;
    asm("fma.rn.f32 %0, %1, %2, %3;" : "=f"(y)
        : "f"(s), "f"(63.0f), "f"(8388608.0f));
    return y;
}

__global__ void __launch_bounds__(896, 1) kann_kernel(
    const float* __restrict__ x,
    const float* __restrict__ w_inner,
    const float* __restrict__ w_outer,
    float* __restrict__ out, int n)
{
    extern __shared__ float smem[];
    float* T1f = smem;           // float4 idx = e*64 + k (e stride 1024 B)
    float* T2f = smem + 16384;   // float4 idx = e*64 + k

    const int tid = threadIdx.x;
    const int nt = blockDim.x;

    // ---------------- build (monomial conversion, both layers) ----------------
    // u_j = c_j * W_j, c = {-9/16, 27/16, -27/16, 9/16}; nodes {-1,-1/3,1/3,1}:
    //   a3 = u0+u1+u2+u3
    //   a2 = (u3-u0) + (u2-u1)/3
    //   a1 = -(u1+u2) - (u0+u3)/9
    //   a0 = (u1-u2)/3 + (u0-u3)/9
    float a[5][4];

    // --- layer 1: stage coalesced into T1 region, convert via regs, store back ---
    for (int f = tid; f < 12352; f += nt) T1f[f] = w_inner[f];
    __syncthreads();
    #pragma unroll
    for (int r = 0; r < 5; ++r) {
        int f = tid + r * nt;
        if (f < 4096) {
            int k = f & 63, e = f >> 6;
            const float* wp = T1f + k * 193 + 3 * e;
            float u0 = -0.5625f * wp[0], u1 = 1.6875f * wp[1];
            float u2 = -1.6875f * wp[2], u3 = 0.5625f * wp[3];
            a[r][3] = (u0 + u1) + (u2 + u3);
            a[r][2] = (u3 - u0) + (1.0f / 3.0f) * (u2 - u1);
            a[r][1] = -(u1 + u2) - (1.0f / 9.0f) * (u0 + u3);
            a[r][0] = (1.0f / 3.0f) * (u1 - u2) + (1.0f / 9.0f) * (u0 - u3);
        }
    }
    __syncthreads();
    #pragma unroll
    for (int r = 0; r < 5; ++r) {
        int f = tid + r * nt;
        if (f < 4096) {
            int k = f & 63, e = f >> 6;
            ((float4*)T1f)[e * 64 + k] = make_float4(a[r][0], a[r][1], a[r][2], a[r][3]);
        }
    }
    // --- layer 2: same, in T2 region ---
    for (int f = tid; f < 12352; f += nt) T2f[f] = w_outer[f];
    __syncthreads();
    #pragma unroll
    for (int r = 0; r < 5; ++r) {
        int f = tid + r * nt;
        if (f < 4096) {
            int k = f & 63, e = f >> 6;
            const float* wp = T2f + k * 193 + 3 * e;
            float u0 = -0.5625f * wp[0], u1 = 1.6875f * wp[1];
            float u2 = -1.6875f * wp[2], u3 = 0.5625f * wp[3];
            a[r][3] = (u0 + u1) + (u2 + u3);
            a[r][2] = (u3 - u0) + (1.0f / 3.0f) * (u2 - u1);
            a[r][1] = -(u1 + u2) - (1.0f / 9.0f) * (u0 + u3);
            a[r][0] = (1.0f / 3.0f) * (u1 - u2) + (1.0f / 9.0f) * (u0 - u3);
        }
    }
    __syncthreads();
    #pragma unroll
    for (int r = 0; r < 5; ++r) {
        int f = tid + r * nt;
        if (f < 4096) {
            int k = f & 63, e = f >> 6;
            ((float4*)T2f)[e * 64 + k] = make_float4(a[r][0], a[r][1], a[r][2], a[r][3]);
        }
    }
    __syncthreads();

    // ---------------- main ----------------
    const char* __restrict__ T1p = (const char*)T1f;
    const char* __restrict__ T2p = (const char*)T2f;

    const int lane = tid & 31;
    const int wid = tid >> 5;
    const int nwarp = gridDim.x * (nt >> 5);
    const int gwarp = wid * gridDim.x + blockIdx.x;
    const int ngroups = n >> 5;

    for (int g = gwarp; g < ngroups; g += nwarp) {
        const int base = g << 5;
        const float xv = x[base + lane];

        // per-group layer-1 params
        const float s1 = __saturatef(fmaf(xv, 64.0f / 63.0f, -0.5f / 63.0f));
        const float y1 = magic_fma(s1);
        const int b1 = (__float_as_int(y1) & 63) << 10;   // byte offset, in-bounds
        const float xt = fmaf(xv, 128.0f, fmaf(y1, -2.0f, 16777215.0f));

        float accA = 0.0f, accB = 0.0f;

        #pragma unroll 4
        for (int i = 0; i < 32; ++i) {
            const int wb = ((lane + i) & 31) << 4;   // byte offset in [0,512)

            // layer 1: 2 LDS.128 + 6 FMA (shared xt), widths (w, w+32)
            const float4 cA = *(const float4*)(T1p + b1 + wb);
            const float4 cB = *(const float4*)(T1p + b1 + 512 + wb);
            const float tA = fmaf(fmaf(fmaf(cA.w, xt, cA.z), xt, cA.y), xt, cA.x);
            const float tB = fmaf(fmaf(fmaf(cB.w, xt, cB.z), xt, cB.y), xt, cB.x);

            // layer 2, width w
            const float sA = __saturatef(fmaf(tA, 64.0f / 63.0f, -0.5f / 63.0f));
            const float yA = magic_fma(sA);
            const int eAb = (__float_as_int(yA) & 63) << 10;
            const float xtA = fmaf(tA, 128.0f, fmaf(yA, -2.0f, 16777215.0f));
            const float4 dA = *(const float4*)(T2p + eAb + wb);
            accA += fmaf(fmaf(fmaf(dA.w, xtA, dA.z), xtA, dA.y), xtA, dA.x);

            // layer 2, width w+32
            const float sB = __saturatef(fmaf(tB, 64.0f / 63.0f, -0.5f / 63.0f));
            const float yB = magic_fma(sB);
            const int eBb = (__float_as_int(yB) & 63) << 10;
            const float xtB = fmaf(tB, 128.0f, fmaf(yB, -2.0f, 16777215.0f));
            const float4 dB = *(const float4*)(T2p + eBb + 512 + wb);
            accB += fmaf(fmaf(fmaf(dB.w, xtB, dB.z), xtB, dB.y), xtB, dB.x);
        }
        out[base + lane] = accA + accB;
    }
}

extern "C" void kernel_launch(void* const* d_in, const int* in_sizes, int n_in,
                              void* d_out, int out_size) {
    const float* x  = (const float*)d_in[0];
    const float* wi = (const float*)d_in[1];
    const float* wo = (const float*)d_in[2];
    float* out = (float*)d_out;
    const int n = in_sizes[0];

    const int smem_bytes = 2 * 16384 * sizeof(float);  // 128 KB
    cudaFuncSetAttribute(kann_kernel, cudaFuncAttributeMaxDynamicSharedMemorySize,
                         smem_bytes);
    kann_kernel<<<148, 896, smem_bytes>>>(x, wi, wo, out, n);
}